// round 5
// baseline (speedup 1.0000x reference)
#include <cuda_runtime.h>
#include <cuda_bf16.h>
#include <math.h>
#include <stdint.h>

typedef __nv_bfloat16 bf16;

// ---------------------------------------------------------------------------
// Problem constants
// ---------------------------------------------------------------------------
#define B_    2
#define S_    2048
#define D_    1024
#define H_    16
#define DH_   64
#define M_TOT (B_ * S_)      // 4096
#define QKV_N (3 * D_)       // 3072
#define K_    1024
#define SCALE 0.125f

// ---------------------------------------------------------------------------
// Scratch (__device__ globals)
// ---------------------------------------------------------------------------
__device__ bf16 g_xhi[M_TOT * D_],  g_xlo[M_TOT * D_];
__device__ bf16 g_wqhi[QKV_N * D_], g_wqlo[QKV_N * D_];
__device__ bf16 g_wohi[D_ * D_],    g_wolo[D_ * D_];
__device__ bf16 g_qhi[M_TOT * QKV_N], g_qlo[M_TOT * QKV_N];  // qkv hi/lo
__device__ bf16 g_ahi[M_TOT * D_],  g_alo[M_TOT * D_];       // attn out hi/lo

// ---------------------------------------------------------------------------
// Helpers
// ---------------------------------------------------------------------------
__device__ __forceinline__ uint32_t sptr(const void* p) {
    return (uint32_t)__cvta_generic_to_shared(p);
}
__device__ __forceinline__ void cp16(uint32_t d, const void* s) {
    asm volatile("cp.async.cg.shared.global [%0], [%1], 16;" :: "r"(d), "l"(s));
}
#define CP_COMMIT() asm volatile("cp.async.commit_group;" ::: "memory")
#define CP_WAIT(n)  asm volatile("cp.async.wait_group %0;" :: "n"(n) : "memory")

__device__ __forceinline__ void ldsm4(uint32_t a, uint32_t r[4]) {
    asm volatile("ldmatrix.sync.aligned.m8n8.x4.shared.b16 {%0,%1,%2,%3}, [%4];"
                 : "=r"(r[0]), "=r"(r[1]), "=r"(r[2]), "=r"(r[3]) : "r"(a));
}
__device__ __forceinline__ void ldsm4t(uint32_t a, uint32_t r[4]) {
    asm volatile("ldmatrix.sync.aligned.m8n8.x4.trans.shared.b16 {%0,%1,%2,%3}, [%4];"
                 : "=r"(r[0]), "=r"(r[1]), "=r"(r[2]), "=r"(r[3]) : "r"(a));
}
__device__ __forceinline__ void mma_bf16(float c[4], const uint32_t a[4],
                                         uint32_t b0, uint32_t b1) {
    asm volatile(
        "mma.sync.aligned.m16n8k16.row.col.f32.bf16.bf16.f32 "
        "{%0,%1,%2,%3}, {%4,%5,%6,%7}, {%8,%9}, {%0,%1,%2,%3};"
        : "+f"(c[0]), "+f"(c[1]), "+f"(c[2]), "+f"(c[3])
        : "r"(a[0]), "r"(a[1]), "r"(a[2]), "r"(a[3]), "r"(b0), "r"(b1));
}
__device__ __forceinline__ void split_pack(float a, float b, uint32_t& hi, uint32_t& lo) {
    __nv_bfloat162 hp = __floats2bfloat162_rn(a, b);
    float ra = a - __bfloat162float(hp.x);
    float rb = b - __bfloat162float(hp.y);
    __nv_bfloat162 lp = __floats2bfloat162_rn(ra, rb);
    hi = *(uint32_t*)&hp;
    lo = *(uint32_t*)&lp;
}

// ---------------------------------------------------------------------------
// Split: fp32 -> bf16 hi + bf16 lo
// ---------------------------------------------------------------------------
__global__ void split_bf16(const float* __restrict__ src,
                           bf16* __restrict__ hi, bf16* __restrict__ lo, int n)
{
    for (int i = blockIdx.x * blockDim.x + threadIdx.x; i < n; i += gridDim.x * blockDim.x) {
        float v = src[i];
        bf16 h = __float2bfloat16(v);
        hi[i] = h;
        lo[i] = __float2bfloat16(v - __bfloat162float(h));
    }
}

// ---------------------------------------------------------------------------
// GEMM: C[M,N] = A[M,K=1024] @ B[N,K=1024]^T  via mma.sync bf16 (3-pass hi/lo)
// 128x128 tile, 8 warps, BK=32, cp.async double-buffered, 2 CTAs/SM.
// ---------------------------------------------------------------------------
#define PKB 80
#define GSTAGE 40960

template<bool SPLIT>
__global__ __launch_bounds__(256, 2) void gemm_mma(
    const bf16* __restrict__ Ahi, const bf16* __restrict__ Alo,
    const bf16* __restrict__ Bhi, const bf16* __restrict__ Blo,
    float* __restrict__ Cf, bf16* __restrict__ Chi, bf16* __restrict__ Clo, int N)
{
    extern __shared__ char smx[];
    const int tid = threadIdx.x, lane = tid & 31, wid = tid >> 5;
    const int bm = blockIdx.y * 128, bn = blockIdx.x * 128;
    const int m0 = (wid >> 2) * 64, n0 = (wid & 3) * 32;

    const bf16* pA[2] = { Ahi + (size_t)bm * K_, Alo + (size_t)bm * K_ };
    const bf16* pB[2] = { Bhi + (size_t)bn * K_, Blo + (size_t)bn * K_ };

    float acc[4][4][4];
    #pragma unroll
    for (int i = 0; i < 4; i++)
        #pragma unroll
        for (int j = 0; j < 4; j++)
            #pragma unroll
            for (int q = 0; q < 4; q++) acc[i][j][q] = 0.0f;

    auto load_stage = [&](int s, int k0) {
        char* base = smx + s * GSTAGE;
        #pragma unroll
        for (int a2 = 0; a2 < 2; a2++) {
            #pragma unroll
            for (int i = 0; i < 2; i++) {
                int idx = tid + i * 256;
                int r = idx >> 2, c = idx & 3;
                cp16(sptr(base + a2 * 10240 + r * PKB + c * 16),
                     pA[a2] + (size_t)r * K_ + k0 + c * 8);
                cp16(sptr(base + 20480 + a2 * 10240 + r * PKB + c * 16),
                     pB[a2] + (size_t)r * K_ + k0 + c * 8);
            }
        }
    };

    load_stage(0, 0);
    CP_COMMIT();

    const int row_in = lane & 7, g = lane >> 3;

    for (int kc = 0; kc < K_ / 32; kc++) {
        if (kc + 1 < K_ / 32) {
            load_stage((kc + 1) & 1, (kc + 1) * 32);
            CP_COMMIT();
            CP_WAIT(1);
        } else {
            CP_WAIT(0);
        }
        __syncthreads();

        char* base = smx + (kc & 1) * GSTAGE;
        uint32_t bAh = sptr(base), bAl = bAh + 10240;
        uint32_t bBh = bAh + 20480, bBl = bAh + 30720;

        #pragma unroll
        for (int ks = 0; ks < 2; ks++) {
            uint32_t ah[4][4], al[4][4];
            #pragma unroll
            for (int mt = 0; mt < 4; mt++) {
                uint32_t off = (uint32_t)(m0 + mt * 16 + row_in + (g & 1) * 8) * PKB
                             + (ks * 16 + (g >> 1) * 8) * 2;
                ldsm4(bAh + off, ah[mt]);
                ldsm4(bAl + off, al[mt]);
            }
            uint32_t bh[2][4], bl[2][4];
            #pragma unroll
            for (int gb = 0; gb < 2; gb++) {
                uint32_t off = (uint32_t)(n0 + gb * 16 + ((g >> 1) & 1) * 8 + row_in) * PKB
                             + (ks * 16 + (g & 1) * 8) * 2;
                ldsm4(bBh + off, bh[gb]);
                ldsm4(bBl + off, bl[gb]);
            }
            #pragma unroll
            for (int mt = 0; mt < 4; mt++)
                #pragma unroll
                for (int nt = 0; nt < 4; nt++) {
                    int gb = nt >> 1, ix = (nt & 1) * 2;
                    mma_bf16(acc[mt][nt], ah[mt], bh[gb][ix], bh[gb][ix + 1]);
                    mma_bf16(acc[mt][nt], ah[mt], bl[gb][ix], bl[gb][ix + 1]);
                    mma_bf16(acc[mt][nt], al[mt], bh[gb][ix], bh[gb][ix + 1]);
                }
        }
        __syncthreads();
    }

    #pragma unroll
    for (int mt = 0; mt < 4; mt++)
        #pragma unroll
        for (int nt = 0; nt < 4; nt++) {
            int row = bm + m0 + mt * 16 + (lane >> 2);
            int col = bn + n0 + nt * 8 + (lane & 3) * 2;
            float* c = acc[mt][nt];
            if (SPLIT) {
                uint32_t h0, l0, h1, l1;
                split_pack(c[0], c[1], h0, l0);
                split_pack(c[2], c[3], h1, l1);
                *(uint32_t*)(Chi + (size_t)row * N + col) = h0;
                *(uint32_t*)(Clo + (size_t)row * N + col) = l0;
                *(uint32_t*)(Chi + (size_t)(row + 8) * N + col) = h1;
                *(uint32_t*)(Clo + (size_t)(row + 8) * N + col) = l1;
            } else {
                *(float2*)(Cf + (size_t)row * N + col) = make_float2(c[0], c[1]);
                *(float2*)(Cf + (size_t)(row + 8) * N + col) = make_float2(c[2], c[3]);
            }
        }
}

// ---------------------------------------------------------------------------
// Flash attention via mma.sync bf16, 8 warps, 128-q tile, double-buffered K/V.
// ---------------------------------------------------------------------------
#define PDD 144
#define SQH 0
#define SQL 18432
#define SKV0 36864
#define KVSTAGE 36864       // KH 0 / KL 9216 / VH 18432 / VL 27648
#define ATT_SMEM (SKV0 + 2 * KVSTAGE)   // 110592

__global__ __launch_bounds__(256) void attn_mma()
{
    extern __shared__ char smx[];
    const int tid = threadIdx.x, lane = tid & 31, warp = tid >> 5;
    const int qt = blockIdx.x;              // 0..15 (128-row q tiles)
    const int b  = blockIdx.y >> 4;
    const int h  = blockIdx.y & 15;
    const int qrow0 = b * S_ + qt * 128;

    const bf16* qh = g_qhi + (size_t)qrow0 * QKV_N + h * DH_;
    const bf16* ql = g_qlo + (size_t)qrow0 * QKV_N + h * DH_;
    const bf16* kh = g_qhi + (size_t)(b * S_) * QKV_N + D_ + h * DH_;
    const bf16* kl = g_qlo + (size_t)(b * S_) * QKV_N + D_ + h * DH_;
    const bf16* vh = g_qhi + (size_t)(b * S_) * QKV_N + 2 * D_ + h * DH_;
    const bf16* vl = g_qlo + (size_t)(b * S_) * QKV_N + 2 * D_ + h * DH_;

    uint32_t sb = sptr(smx);

    // Q tiles: 128 rows x 64 cols, hi+lo
    #pragma unroll
    for (int i = 0; i < 4; i++) {
        int idx = tid + i * 256;            // 0..1023
        int r = idx >> 3, c = idx & 7;
        cp16(sb + SQH + r * PDD + c * 16, qh + (size_t)r * QKV_N + c * 8);
        cp16(sb + SQL + r * PDD + c * 16, ql + (size_t)r * QKV_N + c * 8);
    }
    CP_COMMIT();                            // group A (Q)

    auto ld_kv = [&](int s, int krow) {
        uint32_t base = sb + SKV0 + s * KVSTAGE;
        #pragma unroll
        for (int i = 0; i < 2; i++) {
            int idx = tid + i * 256;        // 0..511
            int r = idx >> 3, c = idx & 7;
            size_t go = (size_t)(krow + r) * QKV_N + c * 8;
            uint32_t so = r * PDD + c * 16;
            cp16(base + so,         kh + go);
            cp16(base + 9216 + so,  kl + go);
            cp16(base + 18432 + so, vh + go);
            cp16(base + 27648 + so, vl + go);
        }
    };

    ld_kv(0, 0);
    CP_COMMIT();                            // group B (kv0)
    CP_WAIT(1);                             // Q done
    __syncthreads();

    const int row_in = lane & 7, g = lane >> 3;

    // Q fragments held in registers for the whole kernel
    uint32_t qa_h[4][4], qa_l[4][4];
    #pragma unroll
    for (int ks = 0; ks < 4; ks++) {
        uint32_t off = (uint32_t)(warp * 16 + row_in + (g & 1) * 8) * PDD
                     + (ks * 16 + (g >> 1) * 8) * 2;
        ldsm4(sb + SQH + off, qa_h[ks]);
        ldsm4(sb + SQL + off, qa_l[ks]);
    }

    float m0 = -1e30f, m1 = -1e30f, l0 = 0.0f, l1 = 0.0f;
    float O[8][4];
    #pragma unroll
    for (int nt = 0; nt < 8; nt++)
        #pragma unroll
        for (int q = 0; q < 4; q++) O[nt][q] = 0.0f;

    for (int kt = 0; kt < S_ / 64; kt++) {
        if (kt + 1 < S_ / 64) {
            ld_kv((kt + 1) & 1, (kt + 1) * 64);
            CP_COMMIT();
            CP_WAIT(1);
        } else {
            CP_WAIT(0);
        }
        __syncthreads();

        uint32_t kvb = sb + SKV0 + (kt & 1) * KVSTAGE;

        // ---- S = Q @ K^T ----
        float s[8][4];
        #pragma unroll
        for (int nt = 0; nt < 8; nt++)
            #pragma unroll
            for (int q = 0; q < 4; q++) s[nt][q] = 0.0f;

        #pragma unroll
        for (int ks = 0; ks < 4; ks++) {
            uint32_t bh[4][4], bl[4][4];
            #pragma unroll
            for (int gb = 0; gb < 4; gb++) {
                uint32_t off = (uint32_t)(gb * 16 + ((g >> 1) & 1) * 8 + row_in) * PDD
                             + (ks * 16 + (g & 1) * 8) * 2;
                ldsm4(kvb + off, bh[gb]);
                ldsm4(kvb + 9216 + off, bl[gb]);
            }
            #pragma unroll
            for (int nt = 0; nt < 8; nt++) {
                int gb = nt >> 1, ix = (nt & 1) * 2;
                mma_bf16(s[nt], qa_h[ks], bh[gb][ix], bh[gb][ix + 1]);
                mma_bf16(s[nt], qa_h[ks], bl[gb][ix], bl[gb][ix + 1]);
                mma_bf16(s[nt], qa_l[ks], bh[gb][ix], bh[gb][ix + 1]);
            }
        }

        // ---- online softmax ----
        float mx0 = -1e30f, mx1 = -1e30f;
        #pragma unroll
        for (int nt = 0; nt < 8; nt++) {
            #pragma unroll
            for (int q = 0; q < 4; q++) s[nt][q] *= SCALE;
            mx0 = fmaxf(mx0, fmaxf(s[nt][0], s[nt][1]));
            mx1 = fmaxf(mx1, fmaxf(s[nt][2], s[nt][3]));
        }
        mx0 = fmaxf(mx0, __shfl_xor_sync(0xffffffffu, mx0, 1));
        mx0 = fmaxf(mx0, __shfl_xor_sync(0xffffffffu, mx0, 2));
        mx1 = fmaxf(mx1, __shfl_xor_sync(0xffffffffu, mx1, 1));
        mx1 = fmaxf(mx1, __shfl_xor_sync(0xffffffffu, mx1, 2));

        float mn0 = fmaxf(m0, mx0), mn1 = fmaxf(m1, mx1);
        float c0 = __expf(m0 - mn0), c1 = __expf(m1 - mn1);
        float sum0 = 0.0f, sum1 = 0.0f;
        #pragma unroll
        for (int nt = 0; nt < 8; nt++) {
            s[nt][0] = __expf(s[nt][0] - mn0); sum0 += s[nt][0];
            s[nt][1] = __expf(s[nt][1] - mn0); sum0 += s[nt][1];
            s[nt][2] = __expf(s[nt][2] - mn1); sum1 += s[nt][2];
            s[nt][3] = __expf(s[nt][3] - mn1); sum1 += s[nt][3];
        }
        sum0 += __shfl_xor_sync(0xffffffffu, sum0, 1);
        sum0 += __shfl_xor_sync(0xffffffffu, sum0, 2);
        sum1 += __shfl_xor_sync(0xffffffffu, sum1, 1);
        sum1 += __shfl_xor_sync(0xffffffffu, sum1, 2);
        l0 = l0 * c0 + sum0;
        l1 = l1 * c1 + sum1;
        m0 = mn0; m1 = mn1;
        #pragma unroll
        for (int nt = 0; nt < 8; nt++) {
            O[nt][0] *= c0; O[nt][1] *= c0;
            O[nt][2] *= c1; O[nt][3] *= c1;
        }

        // ---- O += P @ V ----
        #pragma unroll
        for (int j = 0; j < 4; j++) {
            uint32_t pah[4], pal[4];
            split_pack(s[2 * j][0],     s[2 * j][1],     pah[0], pal[0]);
            split_pack(s[2 * j][2],     s[2 * j][3],     pah[1], pal[1]);
            split_pack(s[2 * j + 1][0], s[2 * j + 1][1], pah[2], pal[2]);
            split_pack(s[2 * j + 1][2], s[2 * j + 1][3], pah[3], pal[3]);

            uint32_t vhf[4][4], vlf[4][4];
            #pragma unroll
            for (int gv = 0; gv < 4; gv++) {
                uint32_t off = (uint32_t)(j * 16 + (g & 1) * 8 + row_in) * PDD
                             + (gv * 16 + (g >> 1) * 8) * 2;
                ldsm4t(kvb + 18432 + off, vhf[gv]);
                ldsm4t(kvb + 27648 + off, vlf[gv]);
            }
            #pragma unroll
            for (int nt = 0; nt < 8; nt++) {
                int gv = nt >> 1, ix = (nt & 1) * 2;
                mma_bf16(O[nt], pah, vhf[gv][ix], vhf[gv][ix + 1]);
                mma_bf16(O[nt], pah, vlf[gv][ix], vlf[gv][ix + 1]);
                mma_bf16(O[nt], pal, vhf[gv][ix], vhf[gv][ix + 1]);
            }
        }
        __syncthreads();
    }

    // ---- epilogue ----
    float inv0 = 1.0f / (l0 + 1e-6f);
    float inv1 = 1.0f / (l1 + 1e-6f);
    int r0g = qrow0 + warp * 16 + (lane >> 2);
    #pragma unroll
    for (int nt = 0; nt < 8; nt++) {
        int col = h * DH_ + nt * 8 + (lane & 3) * 2;
        uint32_t h0, lo0, h1, lo1;
        split_pack(O[nt][0] * inv0, O[nt][1] * inv0, h0, lo0);
        split_pack(O[nt][2] * inv1, O[nt][3] * inv1, h1, lo1);
        *(uint32_t*)(g_ahi + (size_t)r0g * D_ + col) = h0;
        *(uint32_t*)(g_alo + (size_t)r0g * D_ + col) = lo0;
        *(uint32_t*)(g_ahi + (size_t)(r0g + 8) * D_ + col) = h1;
        *(uint32_t*)(g_alo + (size_t)(r0g + 8) * D_ + col) = lo1;
    }
}

// ---------------------------------------------------------------------------
// Launch
// ---------------------------------------------------------------------------
extern "C" void kernel_launch(void* const* d_in, const int* in_sizes, int n_in,
                              void* d_out, int out_size)
{
    const float* x    = (const float*)d_in[0];
    const float* Wqkv = (const float*)d_in[1];
    const float* Wout = (const float*)d_in[2];
    float* out = (float*)d_out;

    bf16 *xhi, *xlo, *wqhi, *wqlo, *wohi, *wolo, *qhi, *qlo, *ahi, *alo;
    cudaGetSymbolAddress((void**)&xhi,  g_xhi);
    cudaGetSymbolAddress((void**)&xlo,  g_xlo);
    cudaGetSymbolAddress((void**)&wqhi, g_wqhi);
    cudaGetSymbolAddress((void**)&wqlo, g_wqlo);
    cudaGetSymbolAddress((void**)&wohi, g_wohi);
    cudaGetSymbolAddress((void**)&wolo, g_wolo);
    cudaGetSymbolAddress((void**)&qhi,  g_qhi);
    cudaGetSymbolAddress((void**)&qlo,  g_qlo);
    cudaGetSymbolAddress((void**)&ahi,  g_ahi);
    cudaGetSymbolAddress((void**)&alo,  g_alo);

    cudaFuncSetAttribute(gemm_mma<true>,
                         cudaFuncAttributeMaxDynamicSharedMemorySize, 2 * GSTAGE);
    cudaFuncSetAttribute(gemm_mma<false>,
                         cudaFuncAttributeMaxDynamicSharedMemorySize, 2 * GSTAGE);
    cudaFuncSetAttribute(attn_mma,
                         cudaFuncAttributeMaxDynamicSharedMemorySize, ATT_SMEM);

    // 0) split inputs
    split_bf16<<<512, 256>>>(x,    xhi,  xlo,  M_TOT * D_);
    split_bf16<<<512, 256>>>(Wqkv, wqhi, wqlo, QKV_N * D_);
    split_bf16<<<256, 256>>>(Wout, wohi, wolo, D_ * D_);

    // 1) qkv = x @ Wqkv^T  -> bf16 hi/lo
    gemm_mma<true><<<dim3(QKV_N / 128, M_TOT / 128), 256, 2 * GSTAGE>>>(
        xhi, xlo, wqhi, wqlo, nullptr, qhi, qlo, QKV_N);

    // 2) attention -> g_ahi/g_alo
    attn_mma<<<dim3(S_ / 128, B_ * H_), 256, ATT_SMEM>>>();

    // 3) out = attn @ Wout^T -> fp32
    gemm_mma<false><<<dim3(D_ / 128, M_TOT / 128), 256, 2 * GSTAGE>>>(
        ahi, alo, wohi, wolo, out, nullptr, nullptr, D_);
}

// round 6
// speedup vs baseline: 1.0104x; 1.0104x over previous
#include <cuda_runtime.h>
#include <cuda_bf16.h>
#include <math.h>
#include <stdint.h>

typedef __nv_bfloat16 bf16;

// ---------------------------------------------------------------------------
// Problem constants
// ---------------------------------------------------------------------------
#define B_    2
#define S_    2048
#define D_    1024
#define H_    16
#define DH_   64
#define M_TOT (B_ * S_)      // 4096
#define QKV_N (3 * D_)       // 3072
#define K_    1024
#define SCALE 0.125f

// ---------------------------------------------------------------------------
// Scratch (__device__ globals)
// ---------------------------------------------------------------------------
__device__ bf16 g_xhi[M_TOT * D_],  g_xlo[M_TOT * D_];
__device__ bf16 g_wqhi[QKV_N * D_], g_wqlo[QKV_N * D_];
__device__ bf16 g_wohi[D_ * D_],    g_wolo[D_ * D_];
__device__ bf16 g_qhi[M_TOT * QKV_N], g_qlo[M_TOT * QKV_N];
__device__ bf16 g_ahi[M_TOT * D_],  g_alo[M_TOT * D_];

// ---------------------------------------------------------------------------
// Helpers
// ---------------------------------------------------------------------------
__device__ __forceinline__ uint32_t sptr(const void* p) {
    return (uint32_t)__cvta_generic_to_shared(p);
}
__device__ __forceinline__ void cp16(uint32_t d, const void* s) {
    asm volatile("cp.async.cg.shared.global [%0], [%1], 16;" :: "r"(d), "l"(s));
}
#define CP_COMMIT() asm volatile("cp.async.commit_group;" ::: "memory")
#define CP_WAIT(n)  asm volatile("cp.async.wait_group %0;" :: "n"(n) : "memory")

__device__ __forceinline__ uint32_t sw128(uint32_t o) {   // Swizzle<3,4,3>
    return o ^ ((o >> 3) & 0x70);
}
__device__ __forceinline__ void ldsm4(uint32_t a, uint32_t r[4]) {
    asm volatile("ldmatrix.sync.aligned.m8n8.x4.shared.b16 {%0,%1,%2,%3}, [%4];"
                 : "=r"(r[0]), "=r"(r[1]), "=r"(r[2]), "=r"(r[3]) : "r"(a));
}
__device__ __forceinline__ void ldsm4t(uint32_t a, uint32_t r[4]) {
    asm volatile("ldmatrix.sync.aligned.m8n8.x4.trans.shared.b16 {%0,%1,%2,%3}, [%4];"
                 : "=r"(r[0]), "=r"(r[1]), "=r"(r[2]), "=r"(r[3]) : "r"(a));
}
__device__ __forceinline__ void mma_bf16(float c[4], const uint32_t a[4],
                                         uint32_t b0, uint32_t b1) {
    asm volatile(
        "mma.sync.aligned.m16n8k16.row.col.f32.bf16.bf16.f32 "
        "{%0,%1,%2,%3}, {%4,%5,%6,%7}, {%8,%9}, {%0,%1,%2,%3};"
        : "+f"(c[0]), "+f"(c[1]), "+f"(c[2]), "+f"(c[3])
        : "r"(a[0]), "r"(a[1]), "r"(a[2]), "r"(a[3]), "r"(b0), "r"(b1));
}
__device__ __forceinline__ void split_pack(float a, float b, uint32_t& hi, uint32_t& lo) {
    __nv_bfloat162 hp = __floats2bfloat162_rn(a, b);
    float ra = a - __bfloat162float(hp.x);
    float rb = b - __bfloat162float(hp.y);
    __nv_bfloat162 lp = __floats2bfloat162_rn(ra, rb);
    hi = *(uint32_t*)&hp;
    lo = *(uint32_t*)&lp;
}

// ---------------------------------------------------------------------------
// Split: fp32 -> bf16 hi + bf16 lo
// ---------------------------------------------------------------------------
__global__ void split_bf16(const float* __restrict__ src,
                           bf16* __restrict__ hi, bf16* __restrict__ lo, int n)
{
    for (int i = blockIdx.x * blockDim.x + threadIdx.x; i < n; i += gridDim.x * blockDim.x) {
        float v = src[i];
        bf16 h = __float2bfloat16(v);
        hi[i] = h;
        lo[i] = __float2bfloat16(v - __bfloat162float(h));
    }
}

// ---------------------------------------------------------------------------
// GEMM: C[M,N] = A[M,K=1024] @ B[N,K=1024]^T, mma.sync bf16 3-pass hi/lo.
// 128x256 CTA tile, 512 threads (16 warps, warp tile 32x64), BK=32,
// cp.async double-buffered. Padded 80B rows (conflict-free, 5r mod 8 cycle).
// ---------------------------------------------------------------------------
#define PKB 80
#define ASZ (128 * PKB)                 // 10240
#define BSZ (256 * PKB)                 // 20480
#define GSTAGE (2 * ASZ + 2 * BSZ)      // 61440

template<bool SPLIT>
__global__ __launch_bounds__(512) void gemm_mma(
    const bf16* __restrict__ Ahi, const bf16* __restrict__ Alo,
    const bf16* __restrict__ Bhi, const bf16* __restrict__ Blo,
    float* __restrict__ Cf, bf16* __restrict__ Chi, bf16* __restrict__ Clo, int N)
{
    extern __shared__ char smx[];
    const int tid = threadIdx.x, lane = tid & 31, wid = tid >> 5;
    const int bm = blockIdx.y * 128, bn = blockIdx.x * 256;
    const int mw = wid >> 2, nw = wid & 3;      // 4x4 warp grid; 32x64 per warp

    const bf16* pA[2] = { Ahi + (size_t)bm * K_, Alo + (size_t)bm * K_ };
    const bf16* pB[2] = { Bhi + (size_t)bn * K_, Blo + (size_t)bn * K_ };

    float acc[2][8][4];
    #pragma unroll
    for (int i = 0; i < 2; i++)
        #pragma unroll
        for (int j = 0; j < 8; j++)
            #pragma unroll
            for (int q = 0; q < 4; q++) acc[i][j][q] = 0.0f;

    auto load_stage = [&](int s, int k0) {
        char* base = smx + s * GSTAGE;
        {   // A: 128 rows x (32 bf16 = 4 x 16B), hi + lo
            int r = tid >> 2, c = tid & 3;
            cp16(sptr(base + r * PKB + c * 16),       pA[0] + (size_t)r * K_ + k0 + c * 8);
            cp16(sptr(base + ASZ + r * PKB + c * 16), pA[1] + (size_t)r * K_ + k0 + c * 8);
        }
        #pragma unroll
        for (int i = 0; i < 2; i++) {   // B: 256 rows
            int idx = tid + i * 512;
            int r = idx >> 2, c = idx & 3;
            cp16(sptr(base + 2 * ASZ + r * PKB + c * 16),
                 pB[0] + (size_t)r * K_ + k0 + c * 8);
            cp16(sptr(base + 2 * ASZ + BSZ + r * PKB + c * 16),
                 pB[1] + (size_t)r * K_ + k0 + c * 8);
        }
    };

    load_stage(0, 0);
    CP_COMMIT();

    const int row_in = lane & 7, g = lane >> 3;

    for (int kc = 0; kc < K_ / 32; kc++) {
        if (kc + 1 < K_ / 32) {
            load_stage((kc + 1) & 1, (kc + 1) * 32);
            CP_COMMIT();
            CP_WAIT(1);
        } else {
            CP_WAIT(0);
        }
        __syncthreads();

        char* base = smx + (kc & 1) * GSTAGE;
        uint32_t bAh = sptr(base),            bAl = bAh + ASZ;
        uint32_t bBh = bAh + 2 * ASZ,         bBl = bBh + BSZ;

        #pragma unroll
        for (int ks = 0; ks < 2; ks++) {
            uint32_t ah[2][4], al[2][4];
            #pragma unroll
            for (int mt = 0; mt < 2; mt++) {
                uint32_t off = (uint32_t)(mw * 32 + mt * 16 + row_in + (g & 1) * 8) * PKB
                             + (ks * 16 + (g >> 1) * 8) * 2;
                ldsm4(bAh + off, ah[mt]);
                ldsm4(bAl + off, al[mt]);
            }
            #pragma unroll
            for (int gb = 0; gb < 4; gb++) {
                uint32_t bh[4], bl[4];
                uint32_t off = (uint32_t)(nw * 64 + gb * 16 + ((g >> 1) & 1) * 8 + row_in) * PKB
                             + (ks * 16 + (g & 1) * 8) * 2;
                ldsm4(bBh + off, bh);
                ldsm4(bBl + off, bl);
                #pragma unroll
                for (int mt = 0; mt < 2; mt++)
                    #pragma unroll
                    for (int hf = 0; hf < 2; hf++) {
                        int nt = gb * 2 + hf, ix = hf * 2;
                        mma_bf16(acc[mt][nt], ah[mt], bh[ix], bh[ix + 1]);
                        mma_bf16(acc[mt][nt], ah[mt], bl[ix], bl[ix + 1]);
                        mma_bf16(acc[mt][nt], al[mt], bh[ix], bh[ix + 1]);
                    }
            }
        }
        __syncthreads();
    }

    #pragma unroll
    for (int mt = 0; mt < 2; mt++)
        #pragma unroll
        for (int nt = 0; nt < 8; nt++) {
            int row = bm + mw * 32 + mt * 16 + (lane >> 2);
            int col = bn + nw * 64 + nt * 8 + (lane & 3) * 2;
            float* c = acc[mt][nt];
            if (SPLIT) {
                uint32_t h0, l0, h1, l1;
                split_pack(c[0], c[1], h0, l0);
                split_pack(c[2], c[3], h1, l1);
                *(uint32_t*)(Chi + (size_t)row * N + col) = h0;
                *(uint32_t*)(Clo + (size_t)row * N + col) = l0;
                *(uint32_t*)(Chi + (size_t)(row + 8) * N + col) = h1;
                *(uint32_t*)(Clo + (size_t)(row + 8) * N + col) = l1;
            } else {
                *(float2*)(Cf + (size_t)row * N + col) = make_float2(c[0], c[1]);
                *(float2*)(Cf + (size_t)(row + 8) * N + col) = make_float2(c[2], c[3]);
            }
        }
}

// ---------------------------------------------------------------------------
// Flash attention: 8 warps, 128-q tile, double-buffered K/V, SW128 swizzled
// smem (96 KB total) -> 2 CTAs/SM.
// ---------------------------------------------------------------------------
#define SQH 0
#define SQL 16384
#define SKV0 32768
#define KVSTAGE 32768       // KH 0 / KL 8192 / VH 16384 / VL 24576 (64x128B ea)
#define ATT_SMEM (SKV0 + 2 * KVSTAGE)   // 98304

__global__ __launch_bounds__(256, 2) void attn_mma()
{
    extern __shared__ char smx[];
    const int tid = threadIdx.x, lane = tid & 31, warp = tid >> 5;
    const int qt = blockIdx.x;
    const int b  = blockIdx.y >> 4;
    const int h  = blockIdx.y & 15;
    const int qrow0 = b * S_ + qt * 128;

    const bf16* qh = g_qhi + (size_t)qrow0 * QKV_N + h * DH_;
    const bf16* ql = g_qlo + (size_t)qrow0 * QKV_N + h * DH_;
    const bf16* kh = g_qhi + (size_t)(b * S_) * QKV_N + D_ + h * DH_;
    const bf16* kl = g_qlo + (size_t)(b * S_) * QKV_N + D_ + h * DH_;
    const bf16* vh = g_qhi + (size_t)(b * S_) * QKV_N + 2 * D_ + h * DH_;
    const bf16* vl = g_qlo + (size_t)(b * S_) * QKV_N + 2 * D_ + h * DH_;

    uint32_t sb = sptr(smx);

    // Q tiles: 128 rows x 128B, hi + lo, SW128
    #pragma unroll
    for (int i = 0; i < 4; i++) {
        int idx = tid + i * 256;
        int r = idx >> 3, c = idx & 7;
        uint32_t so = sw128((uint32_t)(r * 128 + c * 16));
        cp16(sb + SQH + so, qh + (size_t)r * QKV_N + c * 8);
        cp16(sb + SQL + so, ql + (size_t)r * QKV_N + c * 8);
    }
    CP_COMMIT();

    auto ld_kv = [&](int s, int krow) {
        uint32_t base = sb + SKV0 + s * KVSTAGE;
        #pragma unroll
        for (int i = 0; i < 2; i++) {
            int idx = tid + i * 256;
            int r = idx >> 3, c = idx & 7;
            size_t go = (size_t)(krow + r) * QKV_N + c * 8;
            uint32_t so = sw128((uint32_t)(r * 128 + c * 16));
            cp16(base + so,         kh + go);
            cp16(base + 8192 + so,  kl + go);
            cp16(base + 16384 + so, vh + go);
            cp16(base + 24576 + so, vl + go);
        }
    };

    ld_kv(0, 0);
    CP_COMMIT();
    CP_WAIT(1);
    __syncthreads();

    const int row_in = lane & 7, g = lane >> 3;

    uint32_t qa_h[4][4], qa_l[4][4];
    #pragma unroll
    for (int ks = 0; ks < 4; ks++) {
        uint32_t off = sw128((uint32_t)(warp * 16 + row_in + (g & 1) * 8) * 128
                             + (ks * 16 + (g >> 1) * 8) * 2);
        ldsm4(sb + SQH + off, qa_h[ks]);
        ldsm4(sb + SQL + off, qa_l[ks]);
    }

    float m0 = -1e30f, m1 = -1e30f, l0 = 0.0f, l1 = 0.0f;
    float O[8][4];
    #pragma unroll
    for (int nt = 0; nt < 8; nt++)
        #pragma unroll
        for (int q = 0; q < 4; q++) O[nt][q] = 0.0f;

    for (int kt = 0; kt < S_ / 64; kt++) {
        if (kt + 1 < S_ / 64) {
            ld_kv((kt + 1) & 1, (kt + 1) * 64);
            CP_COMMIT();
            CP_WAIT(1);
        } else {
            CP_WAIT(0);
        }
        __syncthreads();

        uint32_t kvb = sb + SKV0 + (kt & 1) * KVSTAGE;

        // ---- S = Q @ K^T ----
        float s[8][4];
        #pragma unroll
        for (int nt = 0; nt < 8; nt++)
            #pragma unroll
            for (int q = 0; q < 4; q++) s[nt][q] = 0.0f;

        #pragma unroll
        for (int ks = 0; ks < 4; ks++) {
            #pragma unroll
            for (int gb = 0; gb < 4; gb++) {
                uint32_t bh[4], bl[4];
                uint32_t off = sw128((uint32_t)(gb * 16 + ((g >> 1) & 1) * 8 + row_in) * 128
                                     + (ks * 16 + (g & 1) * 8) * 2);
                ldsm4(kvb + off, bh);
                ldsm4(kvb + 8192 + off, bl);
                #pragma unroll
                for (int hf = 0; hf < 2; hf++) {
                    int nt = gb * 2 + hf, ix = hf * 2;
                    mma_bf16(s[nt], qa_h[ks], bh[ix], bh[ix + 1]);
                    mma_bf16(s[nt], qa_h[ks], bl[ix], bl[ix + 1]);
                    mma_bf16(s[nt], qa_l[ks], bh[ix], bh[ix + 1]);
                }
            }
        }

        // ---- online softmax ----
        float mx0 = -1e30f, mx1 = -1e30f;
        #pragma unroll
        for (int nt = 0; nt < 8; nt++) {
            #pragma unroll
            for (int q = 0; q < 4; q++) s[nt][q] *= SCALE;
            mx0 = fmaxf(mx0, fmaxf(s[nt][0], s[nt][1]));
            mx1 = fmaxf(mx1, fmaxf(s[nt][2], s[nt][3]));
        }
        mx0 = fmaxf(mx0, __shfl_xor_sync(0xffffffffu, mx0, 1));
        mx0 = fmaxf(mx0, __shfl_xor_sync(0xffffffffu, mx0, 2));
        mx1 = fmaxf(mx1, __shfl_xor_sync(0xffffffffu, mx1, 1));
        mx1 = fmaxf(mx1, __shfl_xor_sync(0xffffffffu, mx1, 2));

        float mn0 = fmaxf(m0, mx0), mn1 = fmaxf(m1, mx1);
        float c0 = __expf(m0 - mn0), c1 = __expf(m1 - mn1);
        float sum0 = 0.0f, sum1 = 0.0f;
        #pragma unroll
        for (int nt = 0; nt < 8; nt++) {
            s[nt][0] = __expf(s[nt][0] - mn0); sum0 += s[nt][0];
            s[nt][1] = __expf(s[nt][1] - mn0); sum0 += s[nt][1];
            s[nt][2] = __expf(s[nt][2] - mn1); sum1 += s[nt][2];
            s[nt][3] = __expf(s[nt][3] - mn1); sum1 += s[nt][3];
        }
        sum0 += __shfl_xor_sync(0xffffffffu, sum0, 1);
        sum0 += __shfl_xor_sync(0xffffffffu, sum0, 2);
        sum1 += __shfl_xor_sync(0xffffffffu, sum1, 1);
        sum1 += __shfl_xor_sync(0xffffffffu, sum1, 2);
        l0 = l0 * c0 + sum0;
        l1 = l1 * c1 + sum1;
        m0 = mn0; m1 = mn1;
        #pragma unroll
        for (int nt = 0; nt < 8; nt++) {
            O[nt][0] *= c0; O[nt][1] *= c0;
            O[nt][2] *= c1; O[nt][3] *= c1;
        }

        // ---- O += P @ V ----
        #pragma unroll
        for (int j = 0; j < 4; j++) {
            uint32_t pah[4], pal[4];
            split_pack(s[2 * j][0],     s[2 * j][1],     pah[0], pal[0]);
            split_pack(s[2 * j][2],     s[2 * j][3],     pah[1], pal[1]);
            split_pack(s[2 * j + 1][0], s[2 * j + 1][1], pah[2], pal[2]);
            split_pack(s[2 * j + 1][2], s[2 * j + 1][3], pah[3], pal[3]);

            #pragma unroll
            for (int gv = 0; gv < 4; gv++) {
                uint32_t vhf[4], vlf[4];
                uint32_t off = sw128((uint32_t)(j * 16 + (g & 1) * 8 + row_in) * 128
                                     + (gv * 16 + (g >> 1) * 8) * 2);
                ldsm4t(kvb + 16384 + off, vhf);
                ldsm4t(kvb + 24576 + off, vlf);
                #pragma unroll
                for (int hf = 0; hf < 2; hf++) {
                    int nt = gv * 2 + hf, ix = hf * 2;
                    mma_bf16(O[nt], pah, vhf[ix], vhf[ix + 1]);
                    mma_bf16(O[nt], pah, vlf[ix], vlf[ix + 1]);
                    mma_bf16(O[nt], pal, vhf[ix], vhf[ix + 1]);
                }
            }
        }
        __syncthreads();
    }

    // ---- epilogue ----
    float inv0 = 1.0f / (l0 + 1e-6f);
    float inv1 = 1.0f / (l1 + 1e-6f);
    int r0g = qrow0 + warp * 16 + (lane >> 2);
    #pragma unroll
    for (int nt = 0; nt < 8; nt++) {
        int col = h * DH_ + nt * 8 + (lane & 3) * 2;
        uint32_t h0, lo0, h1, lo1;
        split_pack(O[nt][0] * inv0, O[nt][1] * inv0, h0, lo0);
        split_pack(O[nt][2] * inv1, O[nt][3] * inv1, h1, lo1);
        *(uint32_t*)(g_ahi + (size_t)r0g * D_ + col) = h0;
        *(uint32_t*)(g_alo + (size_t)r0g * D_ + col) = lo0;
        *(uint32_t*)(g_ahi + (size_t)(r0g + 8) * D_ + col) = h1;
        *(uint32_t*)(g_alo + (size_t)(r0g + 8) * D_ + col) = lo1;
    }
}

// ---------------------------------------------------------------------------
// Launch
// ---------------------------------------------------------------------------
extern "C" void kernel_launch(void* const* d_in, const int* in_sizes, int n_in,
                              void* d_out, int out_size)
{
    const float* x    = (const float*)d_in[0];
    const float* Wqkv = (const float*)d_in[1];
    const float* Wout = (const float*)d_in[2];
    float* out = (float*)d_out;

    bf16 *xhi, *xlo, *wqhi, *wqlo, *wohi, *wolo, *qhi, *qlo, *ahi, *alo;
    cudaGetSymbolAddress((void**)&xhi,  g_xhi);
    cudaGetSymbolAddress((void**)&xlo,  g_xlo);
    cudaGetSymbolAddress((void**)&wqhi, g_wqhi);
    cudaGetSymbolAddress((void**)&wqlo, g_wqlo);
    cudaGetSymbolAddress((void**)&wohi, g_wohi);
    cudaGetSymbolAddress((void**)&wolo, g_wolo);
    cudaGetSymbolAddress((void**)&qhi,  g_qhi);
    cudaGetSymbolAddress((void**)&qlo,  g_qlo);
    cudaGetSymbolAddress((void**)&ahi,  g_ahi);
    cudaGetSymbolAddress((void**)&alo,  g_alo);

    cudaFuncSetAttribute(gemm_mma<true>,
                         cudaFuncAttributeMaxDynamicSharedMemorySize, 2 * GSTAGE);
    cudaFuncSetAttribute(gemm_mma<false>,
                         cudaFuncAttributeMaxDynamicSharedMemorySize, 2 * GSTAGE);
    cudaFuncSetAttribute(attn_mma,
                         cudaFuncAttributeMaxDynamicSharedMemorySize, ATT_SMEM);

    // 0) split inputs
    split_bf16<<<512, 256>>>(x,    xhi,  xlo,  M_TOT * D_);
    split_bf16<<<512, 256>>>(Wqkv, wqhi, wqlo, QKV_N * D_);
    split_bf16<<<256, 256>>>(Wout, wohi, wolo, D_ * D_);

    // 1) qkv = x @ Wqkv^T  -> bf16 hi/lo
    gemm_mma<true><<<dim3(QKV_N / 256, M_TOT / 128), 512, 2 * GSTAGE>>>(
        xhi, xlo, wqhi, wqlo, nullptr, qhi, qlo, QKV_N);

    // 2) attention -> g_ahi/g_alo
    attn_mma<<<dim3(S_ / 128, B_ * H_), 256, ATT_SMEM>>>();

    // 3) out = attn @ Wout^T -> fp32
    gemm_mma<false><<<dim3(D_ / 256, M_TOT / 128), 512, 2 * GSTAGE>>>(
        ahi, alo, wohi, wolo, out, nullptr, nullptr, D_);
}

// round 7
// speedup vs baseline: 1.0676x; 1.0567x over previous
#include <cuda_runtime.h>
#include <cuda_bf16.h>
#include <math.h>
#include <stdint.h>

typedef __nv_bfloat16 bf16;

// ---------------------------------------------------------------------------
// Problem constants
// ---------------------------------------------------------------------------
#define B_    2
#define S_    2048
#define D_    1024
#define H_    16
#define DH_   64
#define M_TOT (B_ * S_)      // 4096
#define QKV_N (3 * D_)       // 3072
#define K_    1024
#define SCALE 0.125f
#define NCHUNK 32            // K_/32

// ---------------------------------------------------------------------------
// Scratch (__device__ globals)
// ---------------------------------------------------------------------------
__device__ bf16 g_xhi[M_TOT * D_],  g_xlo[M_TOT * D_];
__device__ bf16 g_wqhi[QKV_N * D_], g_wqlo[QKV_N * D_];
__device__ bf16 g_wohi[D_ * D_],    g_wolo[D_ * D_];
__device__ bf16 g_qhi[M_TOT * QKV_N], g_qlo[M_TOT * QKV_N];
__device__ bf16 g_ahi[M_TOT * D_],  g_alo[M_TOT * D_];

// ---------------------------------------------------------------------------
// Helpers
// ---------------------------------------------------------------------------
__device__ __forceinline__ uint32_t sptr(const void* p) {
    return (uint32_t)__cvta_generic_to_shared(p);
}
__device__ __forceinline__ void cp16(uint32_t d, const void* s) {
    asm volatile("cp.async.cg.shared.global [%0], [%1], 16;" :: "r"(d), "l"(s));
}
#define CP_COMMIT() asm volatile("cp.async.commit_group;" ::: "memory")
#define CP_WAIT(n)  asm volatile("cp.async.wait_group %0;" :: "n"(n) : "memory")

__device__ __forceinline__ uint32_t sw128(uint32_t o) {   // Swizzle<3,4,3>
    return o ^ ((o >> 3) & 0x70);
}
__device__ __forceinline__ void ldsm4(uint32_t a, uint32_t r[4]) {
    asm volatile("ldmatrix.sync.aligned.m8n8.x4.shared.b16 {%0,%1,%2,%3}, [%4];"
                 : "=r"(r[0]), "=r"(r[1]), "=r"(r[2]), "=r"(r[3]) : "r"(a));
}
__device__ __forceinline__ void ldsm4t(uint32_t a, uint32_t r[4]) {
    asm volatile("ldmatrix.sync.aligned.m8n8.x4.trans.shared.b16 {%0,%1,%2,%3}, [%4];"
                 : "=r"(r[0]), "=r"(r[1]), "=r"(r[2]), "=r"(r[3]) : "r"(a));
}
__device__ __forceinline__ void mma_bf16(float c[4], const uint32_t a[4],
                                         uint32_t b0, uint32_t b1) {
    asm volatile(
        "mma.sync.aligned.m16n8k16.row.col.f32.bf16.bf16.f32 "
        "{%0,%1,%2,%3}, {%4,%5,%6,%7}, {%8,%9}, {%0,%1,%2,%3};"
        : "+f"(c[0]), "+f"(c[1]), "+f"(c[2]), "+f"(c[3])
        : "r"(a[0]), "r"(a[1]), "r"(a[2]), "r"(a[3]), "r"(b0), "r"(b1));
}
__device__ __forceinline__ void split_pack(float a, float b, uint32_t& hi, uint32_t& lo) {
    __nv_bfloat162 hp = __floats2bfloat162_rn(a, b);
    float ra = a - __bfloat162float(hp.x);
    float rb = b - __bfloat162float(hp.y);
    __nv_bfloat162 lp = __floats2bfloat162_rn(ra, rb);
    hi = *(uint32_t*)&hp;
    lo = *(uint32_t*)&lp;
}

// ---------------------------------------------------------------------------
// Split: fp32 -> bf16 hi + bf16 lo
// ---------------------------------------------------------------------------
__global__ void split_bf16(const float* __restrict__ src,
                           bf16* __restrict__ hi, bf16* __restrict__ lo, int n)
{
    for (int i = blockIdx.x * blockDim.x + threadIdx.x; i < n; i += gridDim.x * blockDim.x) {
        float v = src[i];
        bf16 h = __float2bfloat16(v);
        hi[i] = h;
        lo[i] = __float2bfloat16(v - __bfloat162float(h));
    }
}

// ---------------------------------------------------------------------------
// GEMM: C[M,N] = A[M,1024] @ B[N,1024]^T, mma.sync bf16 3-pass hi/lo.
// CTA 128x256, 256 threads (8 warps, 2x4 grid, 64x64 warp tile), BK=32,
// 3-stage cp.async. 85 B smem per mma -> tensor-bound.
// ---------------------------------------------------------------------------
#define PKB 80
#define ASZ (128 * PKB)                 // 10240
#define BSZ (256 * PKB)                 // 20480
#define GSTAGE (2 * ASZ + 2 * BSZ)      // 61440
#define GEMM_SMEM (3 * GSTAGE)          // 184320

template<bool SPLIT>
__global__ __launch_bounds__(256) void gemm_mma(
    const bf16* __restrict__ Ahi, const bf16* __restrict__ Alo,
    const bf16* __restrict__ Bhi, const bf16* __restrict__ Blo,
    float* __restrict__ Cf, bf16* __restrict__ Chi, bf16* __restrict__ Clo, int N)
{
    extern __shared__ char smx[];
    const int tid = threadIdx.x, lane = tid & 31, wid = tid >> 5;
    const int bm = blockIdx.y * 128, bn = blockIdx.x * 256;
    const int m0 = (wid >> 2) * 64, n0 = (wid & 3) * 64;   // warp tile 64x64

    const bf16* pA[2] = { Ahi + (size_t)bm * K_, Alo + (size_t)bm * K_ };
    const bf16* pB[2] = { Bhi + (size_t)bn * K_, Blo + (size_t)bn * K_ };

    float acc[4][8][4];
    #pragma unroll
    for (int i = 0; i < 4; i++)
        #pragma unroll
        for (int j = 0; j < 8; j++)
            #pragma unroll
            for (int q = 0; q < 4; q++) acc[i][j][q] = 0.0f;

    auto load_stage = [&](int s, int k0) {
        char* base = smx + s * GSTAGE;
        #pragma unroll
        for (int i = 0; i < 2; i++) {       // A: 128 rows x 4 x 16B, hi+lo
            int idx = tid + i * 256;
            int r = idx >> 2, c = idx & 3;
            cp16(sptr(base + r * PKB + c * 16),       pA[0] + (size_t)r * K_ + k0 + c * 8);
            cp16(sptr(base + ASZ + r * PKB + c * 16), pA[1] + (size_t)r * K_ + k0 + c * 8);
        }
        #pragma unroll
        for (int i = 0; i < 4; i++) {       // B: 256 rows x 4 x 16B, hi+lo
            int idx = tid + i * 256;
            int r = idx >> 2, c = idx & 3;
            cp16(sptr(base + 2 * ASZ + r * PKB + c * 16),
                 pB[0] + (size_t)r * K_ + k0 + c * 8);
            cp16(sptr(base + 2 * ASZ + BSZ + r * PKB + c * 16),
                 pB[1] + (size_t)r * K_ + k0 + c * 8);
        }
    };

    load_stage(0, 0);  CP_COMMIT();
    load_stage(1, 32); CP_COMMIT();

    const int row_in = lane & 7, g = lane >> 3;

    for (int kc = 0; kc < NCHUNK; kc++) {
        if (kc == NCHUNK - 1) { CP_WAIT(0); } else { CP_WAIT(1); }
        __syncthreads();
        if (kc + 2 < NCHUNK) {
            load_stage((kc + 2) % 3, (kc + 2) * 32);
            CP_COMMIT();
        }

        char* base = smx + (kc % 3) * GSTAGE;
        uint32_t bAh = sptr(base),    bAl = bAh + ASZ;
        uint32_t bBh = bAh + 2 * ASZ, bBl = bBh + BSZ;

        #pragma unroll
        for (int ks = 0; ks < 2; ks++) {
            uint32_t ah[4][4], al[4][4];
            #pragma unroll
            for (int mt = 0; mt < 4; mt++) {
                uint32_t off = (uint32_t)(m0 + mt * 16 + row_in + (g & 1) * 8) * PKB
                             + (ks * 16 + (g >> 1) * 8) * 2;
                ldsm4(bAh + off, ah[mt]);
                ldsm4(bAl + off, al[mt]);
            }
            #pragma unroll
            for (int gb = 0; gb < 4; gb++) {
                uint32_t bh[4], bl[4];
                uint32_t off = (uint32_t)(n0 + gb * 16 + ((g >> 1) & 1) * 8 + row_in) * PKB
                             + (ks * 16 + (g & 1) * 8) * 2;
                ldsm4(bBh + off, bh);
                ldsm4(bBl + off, bl);
                #pragma unroll
                for (int mt = 0; mt < 4; mt++)
                    #pragma unroll
                    for (int hf = 0; hf < 2; hf++) {
                        int nt = gb * 2 + hf, ix = hf * 2;
                        mma_bf16(acc[mt][nt], ah[mt], bh[ix], bh[ix + 1]);
                        mma_bf16(acc[mt][nt], ah[mt], bl[ix], bl[ix + 1]);
                        mma_bf16(acc[mt][nt], al[mt], bh[ix], bh[ix + 1]);
                    }
            }
        }
    }

    #pragma unroll
    for (int mt = 0; mt < 4; mt++)
        #pragma unroll
        for (int nt = 0; nt < 8; nt++) {
            int row = bm + m0 + mt * 16 + (lane >> 2);
            int col = bn + n0 + nt * 8 + (lane & 3) * 2;
            float* c = acc[mt][nt];
            if (SPLIT) {
                uint32_t h0, l0, h1, l1;
                split_pack(c[0], c[1], h0, l0);
                split_pack(c[2], c[3], h1, l1);
                *(uint32_t*)(Chi + (size_t)row * N + col) = h0;
                *(uint32_t*)(Clo + (size_t)row * N + col) = l0;
                *(uint32_t*)(Chi + (size_t)(row + 8) * N + col) = h1;
                *(uint32_t*)(Clo + (size_t)(row + 8) * N + col) = l1;
            } else {
                *(float2*)(Cf + (size_t)row * N + col) = make_float2(c[0], c[1]);
                *(float2*)(Cf + (size_t)(row + 8) * N + col) = make_float2(c[2], c[3]);
            }
        }
}

// ---------------------------------------------------------------------------
// Flash attention: 8 warps, 128-q tile, double-buffered K/V, SW128 swizzled
// smem (96 KB) -> 2 CTAs/SM.  (unchanged from R6)
// ---------------------------------------------------------------------------
#define SQH 0
#define SQL 16384
#define SKV0 32768
#define KVSTAGE 32768
#define ATT_SMEM (SKV0 + 2 * KVSTAGE)   // 98304

__global__ __launch_bounds__(256, 2) void attn_mma()
{
    extern __shared__ char smx[];
    const int tid = threadIdx.x, lane = tid & 31, warp = tid >> 5;
    const int qt = blockIdx.x;
    const int b  = blockIdx.y >> 4;
    const int h  = blockIdx.y & 15;
    const int qrow0 = b * S_ + qt * 128;

    const bf16* qh = g_qhi + (size_t)qrow0 * QKV_N + h * DH_;
    const bf16* ql = g_qlo + (size_t)qrow0 * QKV_N + h * DH_;
    const bf16* kh = g_qhi + (size_t)(b * S_) * QKV_N + D_ + h * DH_;
    const bf16* kl = g_qlo + (size_t)(b * S_) * QKV_N + D_ + h * DH_;
    const bf16* vh = g_qhi + (size_t)(b * S_) * QKV_N + 2 * D_ + h * DH_;
    const bf16* vl = g_qlo + (size_t)(b * S_) * QKV_N + 2 * D_ + h * DH_;

    uint32_t sb = sptr(smx);

    #pragma unroll
    for (int i = 0; i < 4; i++) {
        int idx = tid + i * 256;
        int r = idx >> 3, c = idx & 7;
        uint32_t so = sw128((uint32_t)(r * 128 + c * 16));
        cp16(sb + SQH + so, qh + (size_t)r * QKV_N + c * 8);
        cp16(sb + SQL + so, ql + (size_t)r * QKV_N + c * 8);
    }
    CP_COMMIT();

    auto ld_kv = [&](int s, int krow) {
        uint32_t base = sb + SKV0 + s * KVSTAGE;
        #pragma unroll
        for (int i = 0; i < 2; i++) {
            int idx = tid + i * 256;
            int r = idx >> 3, c = idx & 7;
            size_t go = (size_t)(krow + r) * QKV_N + c * 8;
            uint32_t so = sw128((uint32_t)(r * 128 + c * 16));
            cp16(base + so,         kh + go);
            cp16(base + 8192 + so,  kl + go);
            cp16(base + 16384 + so, vh + go);
            cp16(base + 24576 + so, vl + go);
        }
    };

    ld_kv(0, 0);
    CP_COMMIT();
    CP_WAIT(1);
    __syncthreads();

    const int row_in = lane & 7, g = lane >> 3;

    uint32_t qa_h[4][4], qa_l[4][4];
    #pragma unroll
    for (int ks = 0; ks < 4; ks++) {
        uint32_t off = sw128((uint32_t)(warp * 16 + row_in + (g & 1) * 8) * 128
                             + (ks * 16 + (g >> 1) * 8) * 2);
        ldsm4(sb + SQH + off, qa_h[ks]);
        ldsm4(sb + SQL + off, qa_l[ks]);
    }

    float m0 = -1e30f, m1 = -1e30f, l0 = 0.0f, l1 = 0.0f;
    float O[8][4];
    #pragma unroll
    for (int nt = 0; nt < 8; nt++)
        #pragma unroll
        for (int q = 0; q < 4; q++) O[nt][q] = 0.0f;

    for (int kt = 0; kt < S_ / 64; kt++) {
        if (kt + 1 < S_ / 64) {
            ld_kv((kt + 1) & 1, (kt + 1) * 64);
            CP_COMMIT();
            CP_WAIT(1);
        } else {
            CP_WAIT(0);
        }
        __syncthreads();

        uint32_t kvb = sb + SKV0 + (kt & 1) * KVSTAGE;

        float s[8][4];
        #pragma unroll
        for (int nt = 0; nt < 8; nt++)
            #pragma unroll
            for (int q = 0; q < 4; q++) s[nt][q] = 0.0f;

        #pragma unroll
        for (int ks = 0; ks < 4; ks++) {
            #pragma unroll
            for (int gb = 0; gb < 4; gb++) {
                uint32_t bh[4], bl[4];
                uint32_t off = sw128((uint32_t)(gb * 16 + ((g >> 1) & 1) * 8 + row_in) * 128
                                     + (ks * 16 + (g & 1) * 8) * 2);
                ldsm4(kvb + off, bh);
                ldsm4(kvb + 8192 + off, bl);
                #pragma unroll
                for (int hf = 0; hf < 2; hf++) {
                    int nt = gb * 2 + hf, ix = hf * 2;
                    mma_bf16(s[nt], qa_h[ks], bh[ix], bh[ix + 1]);
                    mma_bf16(s[nt], qa_h[ks], bl[ix], bl[ix + 1]);
                    mma_bf16(s[nt], qa_l[ks], bh[ix], bh[ix + 1]);
                }
            }
        }

        float mx0 = -1e30f, mx1 = -1e30f;
        #pragma unroll
        for (int nt = 0; nt < 8; nt++) {
            #pragma unroll
            for (int q = 0; q < 4; q++) s[nt][q] *= SCALE;
            mx0 = fmaxf(mx0, fmaxf(s[nt][0], s[nt][1]));
            mx1 = fmaxf(mx1, fmaxf(s[nt][2], s[nt][3]));
        }
        mx0 = fmaxf(mx0, __shfl_xor_sync(0xffffffffu, mx0, 1));
        mx0 = fmaxf(mx0, __shfl_xor_sync(0xffffffffu, mx0, 2));
        mx1 = fmaxf(mx1, __shfl_xor_sync(0xffffffffu, mx1, 1));
        mx1 = fmaxf(mx1, __shfl_xor_sync(0xffffffffu, mx1, 2));

        float mn0 = fmaxf(m0, mx0), mn1 = fmaxf(m1, mx1);
        float c0 = __expf(m0 - mn0), c1 = __expf(m1 - mn1);
        float sum0 = 0.0f, sum1 = 0.0f;
        #pragma unroll
        for (int nt = 0; nt < 8; nt++) {
            s[nt][0] = __expf(s[nt][0] - mn0); sum0 += s[nt][0];
            s[nt][1] = __expf(s[nt][1] - mn0); sum0 += s[nt][1];
            s[nt][2] = __expf(s[nt][2] - mn1); sum1 += s[nt][2];
            s[nt][3] = __expf(s[nt][3] - mn1); sum1 += s[nt][3];
        }
        sum0 += __shfl_xor_sync(0xffffffffu, sum0, 1);
        sum0 += __shfl_xor_sync(0xffffffffu, sum0, 2);
        sum1 += __shfl_xor_sync(0xffffffffu, sum1, 1);
        sum1 += __shfl_xor_sync(0xffffffffu, sum1, 2);
        l0 = l0 * c0 + sum0;
        l1 = l1 * c1 + sum1;
        m0 = mn0; m1 = mn1;
        #pragma unroll
        for (int nt = 0; nt < 8; nt++) {
            O[nt][0] *= c0; O[nt][1] *= c0;
            O[nt][2] *= c1; O[nt][3] *= c1;
        }

        #pragma unroll
        for (int j = 0; j < 4; j++) {
            uint32_t pah[4], pal[4];
            split_pack(s[2 * j][0],     s[2 * j][1],     pah[0], pal[0]);
            split_pack(s[2 * j][2],     s[2 * j][3],     pah[1], pal[1]);
            split_pack(s[2 * j + 1][0], s[2 * j + 1][1], pah[2], pal[2]);
            split_pack(s[2 * j + 1][2], s[2 * j + 1][3], pah[3], pal[3]);

            #pragma unroll
            for (int gv = 0; gv < 4; gv++) {
                uint32_t vhf[4], vlf[4];
                uint32_t off = sw128((uint32_t)(j * 16 + (g & 1) * 8 + row_in) * 128
                                     + (gv * 16 + (g >> 1) * 8) * 2);
                ldsm4t(kvb + 16384 + off, vhf);
                ldsm4t(kvb + 24576 + off, vlf);
                #pragma unroll
                for (int hf = 0; hf < 2; hf++) {
                    int nt = gv * 2 + hf, ix = hf * 2;
                    mma_bf16(O[nt], pah, vhf[ix], vhf[ix + 1]);
                    mma_bf16(O[nt], pah, vlf[ix], vlf[ix + 1]);
                    mma_bf16(O[nt], pal, vhf[ix], vhf[ix + 1]);
                }
            }
        }
        __syncthreads();
    }

    float inv0 = 1.0f / (l0 + 1e-6f);
    float inv1 = 1.0f / (l1 + 1e-6f);
    int r0g = qrow0 + warp * 16 + (lane >> 2);
    #pragma unroll
    for (int nt = 0; nt < 8; nt++) {
        int col = h * DH_ + nt * 8 + (lane & 3) * 2;
        uint32_t h0, lo0, h1, lo1;
        split_pack(O[nt][0] * inv0, O[nt][1] * inv0, h0, lo0);
        split_pack(O[nt][2] * inv1, O[nt][3] * inv1, h1, lo1);
        *(uint32_t*)(g_ahi + (size_t)r0g * D_ + col) = h0;
        *(uint32_t*)(g_alo + (size_t)r0g * D_ + col) = lo0;
        *(uint32_t*)(g_ahi + (size_t)(r0g + 8) * D_ + col) = h1;
        *(uint32_t*)(g_alo + (size_t)(r0g + 8) * D_ + col) = lo1;
    }
}

// ---------------------------------------------------------------------------
// Launch
// ---------------------------------------------------------------------------
extern "C" void kernel_launch(void* const* d_in, const int* in_sizes, int n_in,
                              void* d_out, int out_size)
{
    const float* x    = (const float*)d_in[0];
    const float* Wqkv = (const float*)d_in[1];
    const float* Wout = (const float*)d_in[2];
    float* out = (float*)d_out;

    bf16 *xhi, *xlo, *wqhi, *wqlo, *wohi, *wolo, *qhi, *qlo, *ahi, *alo;
    cudaGetSymbolAddress((void**)&xhi,  g_xhi);
    cudaGetSymbolAddress((void**)&xlo,  g_xlo);
    cudaGetSymbolAddress((void**)&wqhi, g_wqhi);
    cudaGetSymbolAddress((void**)&wqlo, g_wqlo);
    cudaGetSymbolAddress((void**)&wohi, g_wohi);
    cudaGetSymbolAddress((void**)&wolo, g_wolo);
    cudaGetSymbolAddress((void**)&qhi,  g_qhi);
    cudaGetSymbolAddress((void**)&qlo,  g_qlo);
    cudaGetSymbolAddress((void**)&ahi,  g_ahi);
    cudaGetSymbolAddress((void**)&alo,  g_alo);

    cudaFuncSetAttribute(gemm_mma<true>,
                         cudaFuncAttributeMaxDynamicSharedMemorySize, GEMM_SMEM);
    cudaFuncSetAttribute(gemm_mma<false>,
                         cudaFuncAttributeMaxDynamicSharedMemorySize, GEMM_SMEM);
    cudaFuncSetAttribute(attn_mma,
                         cudaFuncAttributeMaxDynamicSharedMemorySize, ATT_SMEM);

    // 0) split inputs
    split_bf16<<<512, 256>>>(x,    xhi,  xlo,  M_TOT * D_);
    split_bf16<<<512, 256>>>(Wqkv, wqhi, wqlo, QKV_N * D_);
    split_bf16<<<256, 256>>>(Wout, wohi, wolo, D_ * D_);

    // 1) qkv = x @ Wqkv^T  -> bf16 hi/lo
    gemm_mma<true><<<dim3(QKV_N / 256, M_TOT / 128), 256, GEMM_SMEM>>>(
        xhi, xlo, wqhi, wqlo, nullptr, qhi, qlo, QKV_N);

    // 2) attention -> g_ahi/g_alo
    attn_mma<<<dim3(S_ / 128, B_ * H_), 256, ATT_SMEM>>>();

    // 3) out = attn @ Wout^T -> fp32
    gemm_mma<false><<<dim3(D_ / 256, M_TOT / 128), 256, GEMM_SMEM>>>(
        ahi, alo, wohi, wolo, out, nullptr, nullptr, D_);
}